// round 16
// baseline (speedup 1.0000x reference)
#include <cuda_runtime.h>
#include <cuda_bf16.h>
#include <math.h>
#include <stdint.h>

// Problem constants
#define BATCH 16
#define LSEQ  256
#define DMDL  1024           // dm == di
#define DTOT  68             // dtr + 2*n
#define DTR   64
#define MROWS (BATCH*LSEQ)   // 4096

// ---------------- scratch (device globals; no allocations allowed) ----------
__device__ float g_xz [BATCH*LSEQ*2*DMDL];
__device__ float g_xi [BATCH*LSEQ*DMDL];
__device__ float g_dbl[BATCH*LSEQ*DTOT];
__device__ float g_dt [BATCH*LSEQ*DMDL];
__device__ float g_y  [BATCH*LSEQ*DMDL];
__device__ float g_s  [BATCH*LSEQ*DMDL];
__device__ float g_t  [BATCH*LSEQ*DMDL];
__device__ float g_r  [BATCH*LSEQ*DMDL];
__device__ float g_r2 [BATCH*LSEQ*DMDL];

// ---------------- helpers ----------------------------------------------------
__device__ __forceinline__ float silu_f(float v) {
    return v / (1.0f + expf(-v));
}
__device__ __forceinline__ float softplus_f(float v) {
    return fmaxf(v, 0.0f) + log1pf(expf(-fabsf(v)));
}
__device__ __forceinline__ unsigned pack_bf2(__nv_bfloat16 a, __nv_bfloat16 b) {
    __nv_bfloat162 t(a, b);          // a -> low half, b -> high half
    return *reinterpret_cast<unsigned*>(&t);
}
__device__ __forceinline__ void bf16_split(float x, __nv_bfloat16& h, __nv_bfloat16& l) {
    h = __float2bfloat16_rn(x);
    l = __float2bfloat16_rn(x - __bfloat162float(h));
}
__device__ __forceinline__ void split_pack4(float4 v, uint2& h, uint2& l) {
    __nv_bfloat16 hx, hy, hz, hw, lx, ly, lz, lw;
    bf16_split(v.x, hx, lx);
    bf16_split(v.y, hy, ly);
    bf16_split(v.z, hz, lz);
    bf16_split(v.w, hw, lw);
    h.x = pack_bf2(hx, hy); h.y = pack_bf2(hz, hw);
    l.x = pack_bf2(lx, ly); l.y = pack_bf2(lz, lw);
}
__device__ __forceinline__ void mma_bf16(float* c, const unsigned* a, const unsigned* b) {
    asm volatile(
        "mma.sync.aligned.m16n8k16.row.col.f32.bf16.bf16.f32 "
        "{%0,%1,%2,%3},{%4,%5,%6,%7},{%8,%9},{%0,%1,%2,%3};\n"
        : "+f"(c[0]), "+f"(c[1]), "+f"(c[2]), "+f"(c[3])
        : "r"(a[0]), "r"(a[1]), "r"(a[2]), "r"(a[3]), "r"(b[0]), "r"(b[1]));
}

// ================== 3x-bf16 HMMA GEMM, BT (X @ W^T) ===========================
// C[m,n] = epi( sum_k A[m,k]*B[n,k] );  M%128==0, K%16==0, N arbitrary (guarded)
// KP=12: fragment LDS g*12+tg mod 32 all distinct -> conflict-free; uint2 STS.
// Double-buffered smem, ONE barrier per k-iteration.
// EPI: 0 none, 2 silu(v+bias[n]), 3 softplus(v+bias[n])
#define GBM 128
#define GBN 128
#define GBK 16
#define KP  12
#define TG_TILE_U (GBM*KP)              // u32 per tile
#define TG_BUF_U  (4*TG_TILE_U)         // AsH, AsL, BsH, BsL
#define TG_SMEM_B (2*TG_BUF_U*4)        // 49152 bytes

template<int EPI>
__global__ __launch_bounds__(256, 2)
void tgemm_kernel(const float* __restrict__ A, int lda,
                  const float* __restrict__ B, int ldb,
                  const float* __restrict__ bias,
                  float* __restrict__ C, int ldc,
                  int M, int N, int K)
{
    extern __shared__ unsigned tsm[];

    const int m0 = blockIdx.y * GBM;
    const int n0 = blockIdx.x * GBN;
    const int tid = threadIdx.x;
    const int warp = tid >> 5, lane = tid & 31;
    const int wm = warp & 1;
    const int wn = warp >> 1;
    const int g  = lane >> 2;
    const int tg = lane & 3;

    float acc[4][4][4];
    #pragma unroll
    for (int mi = 0; mi < 4; mi++)
        #pragma unroll
        for (int ni = 0; ni < 4; ni++)
            #pragma unroll
            for (int q = 0; q < 4; q++) acc[mi][ni][q] = 0.0f;

    const int a_r  = tid >> 2;          // 0..63 (+64)
    const int a_c4 = (tid & 3) * 4;     // k: 0,4,8,12
    const int a_cw = a_c4 >> 1;         // u32 col: 0,2,4,6

    const bool bok0 = (n0 + a_r)      < N;
    const bool bok1 = (n0 + a_r + 64) < N;

    float4 pa[2], pb[2];
    const float4 fz = make_float4(0.f, 0.f, 0.f, 0.f);

    // prologue prefetch (k-tile 0)
    #pragma unroll
    for (int i = 0; i < 2; i++) {
        pa[i] = *(const float4*)(A + (size_t)(m0 + a_r + i * 64) * lda + a_c4);
        const bool ok = i ? bok1 : bok0;
        pb[i] = ok ? *(const float4*)(B + (size_t)(n0 + a_r + i * 64) * ldb + a_c4) : fz;
    }

    const int nIter = K / GBK;
    for (int it = 0; it < nIter; it++) {
        unsigned* AsH = tsm + (it & 1) * TG_BUF_U;
        unsigned* AsL = AsH + TG_TILE_U;
        unsigned* BsH = AsL + TG_TILE_U;
        unsigned* BsL = BsH + TG_TILE_U;

        // store staged tile (uint2 stores; KP even so rows 8B-aligned)
        #pragma unroll
        for (int i = 0; i < 2; i++) {
            uint2 h, l;
            const int ar = (a_r + i * 64) * KP + a_cw;
            split_pack4(pa[i], h, l);
            *(uint2*)&AsH[ar] = h;
            *(uint2*)&AsL[ar] = l;
            split_pack4(pb[i], h, l);
            *(uint2*)&BsH[ar] = h;
            *(uint2*)&BsL[ar] = l;
        }
        __syncthreads();

        // prefetch next tile (overlaps compute)
        const int kn = (it + 1) * GBK;
        if (kn < K) {
            #pragma unroll
            for (int i = 0; i < 2; i++) {
                pa[i] = *(const float4*)(A + (size_t)(m0 + a_r + i * 64) * lda + kn + a_c4);
                const bool ok = i ? bok1 : bok0;
                pb[i] = ok ? *(const float4*)(B + (size_t)(n0 + a_r + i * 64) * ldb + kn + a_c4) : fz;
            }
        }

        // compute this BK=16 tile
        {
            unsigned bh[4][2], bl[4][2];
            #pragma unroll
            for (int ni = 0; ni < 4; ni++) {
                const int c = (wn * 32 + ni * 8 + g) * KP;
                bh[ni][0] = BsH[c + tg];
                bh[ni][1] = BsH[c + tg + 4];
                bl[ni][0] = BsL[c + tg];
                bl[ni][1] = BsL[c + tg + 4];
            }
            #pragma unroll
            for (int mi = 0; mi < 4; mi++) {
                const int r0 = (wm * 64 + mi * 16 + g) * KP;
                const int r8 = r0 + 8 * KP;
                unsigned ah[4], al[4];
                ah[0] = AsH[r0 + tg];
                ah[1] = AsH[r8 + tg];
                ah[2] = AsH[r0 + tg + 4];
                ah[3] = AsH[r8 + tg + 4];
                al[0] = AsL[r0 + tg];
                al[1] = AsL[r8 + tg];
                al[2] = AsL[r0 + tg + 4];
                al[3] = AsL[r8 + tg + 4];
                #pragma unroll
                for (int ni = 0; ni < 4; ni++) {
                    mma_bf16(acc[mi][ni], ah, bh[ni]);   // hi*hi
                    mma_bf16(acc[mi][ni], ah, bl[ni]);   // hi*lo
                    mma_bf16(acc[mi][ni], al, bh[ni]);   // lo*hi
                }
            }
        }
        // single barrier per iter: next iter writes the OTHER buffer, whose
        // last readers passed THIS barrier only after finishing those reads.
    }

    // epilogue (N-guarded)
    #pragma unroll
    for (int mi = 0; mi < 4; mi++) {
        const int r = m0 + wm * 64 + mi * 16 + g;
        #pragma unroll
        for (int ni = 0; ni < 4; ni++) {
            const int c = n0 + wn * 32 + ni * 8 + tg * 2;
            if (c >= N) continue;
            float v0 = acc[mi][ni][0];
            float v1 = acc[mi][ni][1];
            float v2 = acc[mi][ni][2];
            float v3 = acc[mi][ni][3];
            if (EPI == 2 || EPI == 3) {
                const float bb0 = bias[c], bb1 = bias[c + 1];
                v0 += bb0; v1 += bb1; v2 += bb0; v3 += bb1;
            }
            if (EPI == 2) {
                v0 = silu_f(v0); v1 = silu_f(v1);
                v2 = silu_f(v2); v3 = silu_f(v3);
            }
            if (EPI == 3) {
                v0 = softplus_f(v0); v1 = softplus_f(v1);
                v2 = softplus_f(v2); v3 = softplus_f(v3);
            }
            *(float2*)&C[(size_t)r * ldc + c]       = make_float2(v0, v1);
            *(float2*)&C[(size_t)(r + 8) * ldc + c] = make_float2(v2, v3);
        }
    }
}

// ================== 3x-bf16 HMMA GEMM, NN channel-mix (W_mid/W_res) ==========
// C[m,n] = silu( sum_k A[m,k]*B[k,n] ), batched over blockIdx.z.
// KP2=13: odd u16 stride kills B-scatter store conflicts (measured 63->38us).
#define KP2 13

__global__ __launch_bounds__(256, 2)
void ngemm_kernel(const float* __restrict__ A, int lda,
                  const float* __restrict__ B, int ldb, size_t sB,
                  float* __restrict__ C, int ldc, size_t sC,
                  int M, int N, int K)
{
    __shared__ unsigned As_hi[GBM][KP2];
    __shared__ unsigned As_lo[GBM][KP2];
    __shared__ unsigned Bs_hi[GBN][KP2];
    __shared__ unsigned Bs_lo[GBN][KP2];

    const int bz = blockIdx.z;
    B += sB * bz; C += sC * bz;

    const int m0 = blockIdx.y * GBM;
    const int n0 = blockIdx.x * GBN;
    const int tid = threadIdx.x;
    const int warp = tid >> 5, lane = tid & 31;
    const int wm = warp & 1;
    const int wn = warp >> 1;
    const int g  = lane >> 2;
    const int tg = lane & 3;

    float acc[4][4][4];
    #pragma unroll
    for (int mi = 0; mi < 4; mi++)
        #pragma unroll
        for (int ni = 0; ni < 4; ni++)
            #pragma unroll
            for (int q = 0; q < 4; q++) acc[mi][ni][q] = 0.0f;

    const int a_r  = tid >> 2;
    const int a_c4 = (tid & 3) * 4;
    const int a_cw = a_c4 >> 1;
    const int b_kr = tid >> 5;
    const int b_nc = (tid & 31) * 4;

    float4 pa[2], pb[2];

    #pragma unroll
    for (int i = 0; i < 2; i++) {
        pa[i] = *(const float4*)(A + (size_t)(m0 + a_r + i * 64) * lda + a_c4);
        pb[i] = *(const float4*)(B + (size_t)(b_kr + i * 8) * ldb + n0 + b_nc);
    }

    unsigned short* Bs_hi16 = (unsigned short*)Bs_hi;
    unsigned short* Bs_lo16 = (unsigned short*)Bs_lo;

    int k0 = 0;
    while (true) {
        #pragma unroll
        for (int i = 0; i < 2; i++) {
            uint2 h, l;
            split_pack4(pa[i], h, l);
            const int ar = a_r + i * 64;
            As_hi[ar][a_cw]     = h.x;
            As_hi[ar][a_cw + 1] = h.y;
            As_lo[ar][a_cw]     = l.x;
            As_lo[ar][a_cw + 1] = l.y;

            const int k = b_kr + i * 8;
            const float* pv = &pb[i].x;
            #pragma unroll
            for (int j = 0; j < 4; j++) {
                __nv_bfloat16 hh, ll;
                bf16_split(pv[j], hh, ll);
                Bs_hi16[(b_nc + j) * (2 * KP2) + k] = *(unsigned short*)&hh;
                Bs_lo16[(b_nc + j) * (2 * KP2) + k] = *(unsigned short*)&ll;
            }
        }
        __syncthreads();

        const int kn = k0 + GBK;
        const bool more = kn < K;
        if (more) {
            #pragma unroll
            for (int i = 0; i < 2; i++) {
                pa[i] = *(const float4*)(A + (size_t)(m0 + a_r + i * 64) * lda + kn + a_c4);
                pb[i] = *(const float4*)(B + (size_t)(kn + b_kr + i * 8) * ldb + n0 + b_nc);
            }
        }

        {
            unsigned bh[4][2], bl[4][2];
            #pragma unroll
            for (int ni = 0; ni < 4; ni++) {
                const int c = wn * 32 + ni * 8 + g;
                bh[ni][0] = Bs_hi[c][tg];
                bh[ni][1] = Bs_hi[c][tg + 4];
                bl[ni][0] = Bs_lo[c][tg];
                bl[ni][1] = Bs_lo[c][tg + 4];
            }
            #pragma unroll
            for (int mi = 0; mi < 4; mi++) {
                const int r = wm * 64 + mi * 16 + g;
                unsigned ah[4], al[4];
                ah[0] = As_hi[r    ][tg];
                ah[1] = As_hi[r + 8][tg];
                ah[2] = As_hi[r    ][tg + 4];
                ah[3] = As_hi[r + 8][tg + 4];
                al[0] = As_lo[r    ][tg];
                al[1] = As_lo[r + 8][tg];
                al[2] = As_lo[r    ][tg + 4];
                al[3] = As_lo[r + 8][tg + 4];
                #pragma unroll
                for (int ni = 0; ni < 4; ni++) {
                    mma_bf16(acc[mi][ni], ah, bh[ni]);
                    mma_bf16(acc[mi][ni], ah, bl[ni]);
                    mma_bf16(acc[mi][ni], al, bh[ni]);
                }
            }
        }

        if (!more) break;
        __syncthreads();
        k0 = kn;
    }

    #pragma unroll
    for (int mi = 0; mi < 4; mi++) {
        const int r = m0 + wm * 64 + mi * 16 + g;
        #pragma unroll
        for (int ni = 0; ni < 4; ni++) {
            const int c = n0 + wn * 32 + ni * 8 + tg * 2;
            float v0 = silu_f(acc[mi][ni][0]);
            float v1 = silu_f(acc[mi][ni][1]);
            float v2 = silu_f(acc[mi][ni][2]);
            float v3 = silu_f(acc[mi][ni][3]);
            *(float2*)&C[(size_t)r * ldc + c]       = make_float2(v0, v1);
            *(float2*)&C[(size_t)(r + 8) * ldc + c] = make_float2(v2, v3);
        }
    }
}

// ---------------- depthwise causal conv (k=4) + silu --------------------------
__global__ __launch_bounds__(256)
void conv_silu_kernel(const float* __restrict__ xz,
                      const float* __restrict__ convw,
                      const float* __restrict__ convb,
                      float* __restrict__ xi)
{
    const int idx = blockIdx.x * 256 + threadIdx.x;
    const int d = idx & (DMDL - 1);
    const int bl = idx >> 10;
    const int l = bl & (LSEQ - 1);
    const int b = bl >> 8;

    float w0 = convw[d * 4 + 0], w1 = convw[d * 4 + 1];
    float w2 = convw[d * 4 + 2], w3 = convw[d * 4 + 3];

    const size_t base = ((size_t)b * LSEQ) * (2 * DMDL) + d;
    float acc = convb[d];
    if (l >= 3) acc = fmaf(w0, xz[base + (size_t)(l - 3) * (2 * DMDL)], acc);
    if (l >= 2) acc = fmaf(w1, xz[base + (size_t)(l - 2) * (2 * DMDL)], acc);
    if (l >= 1) acc = fmaf(w2, xz[base + (size_t)(l - 1) * (2 * DMDL)], acc);
    acc = fmaf(w3, xz[base + (size_t)l * (2 * DMDL)], acc);

    xi[idx] = silu_f(acc);
}

// ---------------- selective-scan (n=2) fused with skip + gate -----------------
__global__ __launch_bounds__(256)
void scan_kernel(const float* __restrict__ dt,
                 const float* __restrict__ xi,
                 const float* __restrict__ xz,
                 const float* __restrict__ dbl,
                 const float* __restrict__ Alog,
                 const float* __restrict__ Dp,
                 float* __restrict__ y)
{
    const int b = blockIdx.x >> 2;
    const int chunk = blockIdx.x & 3;
    const int d = chunk * 256 + threadIdx.x;

    const float A0 = -expf(Alog[d * 2 + 0]);
    const float A1 = -expf(Alog[d * 2 + 1]);
    const float Dd = Dp[d];

    float h0 = 0.0f, h1 = 0.0f;

    #pragma unroll 4
    for (int l = 0; l < LSEQ; l++) {
        const int bl = b * LSEQ + l;
        const size_t idx = (size_t)bl * DMDL + d;
        const float dtv = dt[idx];
        const float xiv = xi[idx];
        const float zv  = xz[(size_t)bl * (2 * DMDL) + DMDL + d];
        const float* bc = dbl + (size_t)bl * DTOT + DTR;
        const float B0 = bc[0], B1 = bc[1], C0 = bc[2], C1 = bc[3];

        const float dBx = dtv * xiv;
        h0 = fmaf(expf(dtv * A0), h0, dBx * B0);
        h1 = fmaf(expf(dtv * A1), h1, dBx * B1);

        float yv = fmaf(h0, C0, h1 * C1);
        yv = fmaf(Dd, xiv, yv);
        y[idx] = yv * silu_f(zv);
    }
}

// ---------------- LayerNorm (in-place) ----------------------------------------
__global__ __launch_bounds__(256)
void ln_kernel(float* __restrict__ x,
               const float* __restrict__ g,
               const float* __restrict__ b)
{
    __shared__ float red[256];
    const int tid = threadIdx.x;
    float* p = x + (size_t)blockIdx.x * DMDL;

    float v[4];
    float s = 0.0f;
    #pragma unroll
    for (int i = 0; i < 4; i++) { v[i] = p[tid + i * 256]; s += v[i]; }

    red[tid] = s; __syncthreads();
    for (int o = 128; o > 0; o >>= 1) {
        if (tid < o) red[tid] += red[tid + o];
        __syncthreads();
    }
    const float mean = red[0] * (1.0f / DMDL);
    __syncthreads();

    float sq = 0.0f;
    #pragma unroll
    for (int i = 0; i < 4; i++) { float dd = v[i] - mean; sq += dd * dd; }
    red[tid] = sq; __syncthreads();
    for (int o = 128; o > 0; o >>= 1) {
        if (tid < o) red[tid] += red[tid + o];
        __syncthreads();
    }
    const float rstd = rsqrtf(red[0] * (1.0f / DMDL) + 1e-5f);

    #pragma unroll
    for (int i = 0; i < 4; i++) {
        const int c = tid + i * 256;
        p[c] = (v[i] - mean) * rstd * g[c] + b[c];
    }
}

// ---------------- final fused add + silu --------------------------------------
__global__ __launch_bounds__(256)
void final_kernel(const float* __restrict__ s,
                  const float* __restrict__ r,
                  float* __restrict__ out)
{
    const int i = blockIdx.x * 256 + threadIdx.x;
    out[i] = silu_f(s[i] + r[i]);
}

// ---------------- host orchestration ------------------------------------------
static void run_mamba(const float* X,
                      const float* Win, const float* convw, const float* convb,
                      const float* Wx, const float* Wdt, const float* bdt,
                      const float* Alog, const float* Dp, const float* Wout,
                      float* xz, float* xi, float* dbl, float* dt, float* y,
                      float* out)
{
    dim3 blk(256);
    // xz = X @ Win^T   (4096 x 2048, K=1024)
    tgemm_kernel<0><<<dim3((2 * DMDL) / GBN, MROWS / GBM), blk, TG_SMEM_B>>>(
        X, DMDL, Win, DMDL, nullptr, xz, 2 * DMDL, MROWS, 2 * DMDL, DMDL);
    // xi = silu(conv(xz[:,:,:di]))
    conv_silu_kernel<<<(MROWS * DMDL) / 256, blk>>>(xz, convw, convb, xi);
    // dbl = xi @ Wx^T  (4096 x 68, K=1024) — tensor with N-guard
    tgemm_kernel<0><<<dim3(1, MROWS / GBM), blk, TG_SMEM_B>>>(
        xi, DMDL, Wx, DMDL, nullptr, dbl, DTOT, MROWS, DTOT, DMDL);
    // dt = softplus(dbl[:,:64] @ Wdt^T + bdt)  (4096 x 1024, K=64) — tensor
    tgemm_kernel<3><<<dim3(DMDL / GBN, MROWS / GBM), blk, TG_SMEM_B>>>(
        dbl, DTOT, Wdt, DTR, bdt, dt, DMDL, MROWS, DMDL, DTR);
    // selective scan + skip + gate
    scan_kernel<<<BATCH * (DMDL / 256), blk>>>(dt, xi, xz, dbl, Alog, Dp, y);
    // out = y @ Wout^T  (4096 x 1024, K=1024)
    tgemm_kernel<0><<<dim3(DMDL / GBN, MROWS / GBM), blk, TG_SMEM_B>>>(
        y, DMDL, Wout, DMDL, nullptr, out, DMDL, MROWS, DMDL, DMDL);
}

extern "C" void kernel_launch(void* const* d_in, const int* in_sizes, int n_in,
                              void* d_out, int out_size)
{
    (void)in_sizes; (void)n_in; (void)out_size;

    const float* x        = (const float*)d_in[0];
    const float* m1_Win   = (const float*)d_in[1];
    const float* m1_convw = (const float*)d_in[2];
    const float* m1_convb = (const float*)d_in[3];
    const float* m1_Wx    = (const float*)d_in[4];
    const float* m1_Wdt   = (const float*)d_in[5];
    const float* m1_bdt   = (const float*)d_in[6];
    const float* m1_Alog  = (const float*)d_in[7];
    const float* m1_D     = (const float*)d_in[8];
    const float* m1_Wout  = (const float*)d_in[9];
    const float* m2_Win   = (const float*)d_in[10];
    const float* m2_convw = (const float*)d_in[11];
    const float* m2_convb = (const float*)d_in[12];
    const float* m2_Wx    = (const float*)d_in[13];
    const float* m2_Wdt   = (const float*)d_in[14];
    const float* m2_bdt   = (const float*)d_in[15];
    const float* m2_Alog  = (const float*)d_in[16];
    const float* m2_D     = (const float*)d_in[17];
    const float* m2_Wout  = (const float*)d_in[18];
    const float* ln1_g    = (const float*)d_in[19];
    const float* ln1_b    = (const float*)d_in[20];
    const float* ln2_g    = (const float*)d_in[21];
    const float* ln2_b    = (const float*)d_in[22];
    const float* W_mid    = (const float*)d_in[23];
    const float* W_spa    = (const float*)d_in[24];
    const float* b_spa    = (const float*)d_in[25];
    const float* W_res    = (const float*)d_in[26];
    float* out = (float*)d_out;

    // raise dynamic smem cap for tgemm (host-side attribute; no allocation)
    static bool attr_done = false;
    if (!attr_done) {
        cudaFuncSetAttribute((const void*)tgemm_kernel<0>, cudaFuncAttributeMaxDynamicSharedMemorySize, TG_SMEM_B);
        cudaFuncSetAttribute((const void*)tgemm_kernel<2>, cudaFuncAttributeMaxDynamicSharedMemorySize, TG_SMEM_B);
        cudaFuncSetAttribute((const void*)tgemm_kernel<3>, cudaFuncAttributeMaxDynamicSharedMemorySize, TG_SMEM_B);
        attr_done = true;
    }

    void *p_xz, *p_xi, *p_dbl, *p_dt, *p_y, *p_s, *p_t, *p_r, *p_r2;
    cudaGetSymbolAddress(&p_xz,  g_xz);
    cudaGetSymbolAddress(&p_xi,  g_xi);
    cudaGetSymbolAddress(&p_dbl, g_dbl);
    cudaGetSymbolAddress(&p_dt,  g_dt);
    cudaGetSymbolAddress(&p_y,   g_y);
    cudaGetSymbolAddress(&p_s,   g_s);
    cudaGetSymbolAddress(&p_t,   g_t);
    cudaGetSymbolAddress(&p_r,   g_r);
    cudaGetSymbolAddress(&p_r2,  g_r2);
    float* xz = (float*)p_xz;  float* xi = (float*)p_xi;  float* dbl = (float*)p_dbl;
    float* dt = (float*)p_dt;  float* y  = (float*)p_y;   float* s   = (float*)p_s;
    float* t  = (float*)p_t;   float* r  = (float*)p_r;   float* r2  = (float*)p_r2;

    dim3 blk(256);
    const size_t bstride = (size_t)LSEQ * DMDL;

    // ---- stage 1: mamba1 -> s
    run_mamba(x, m1_Win, m1_convw, m1_convb, m1_Wx, m1_Wdt, m1_bdt,
              m1_Alog, m1_D, m1_Wout, xz, xi, dbl, dt, y, s);
    ln_kernel<<<MROWS, blk>>>(s, ln1_g, ln1_b);
    // t[b,o,sp] = silu(sum_c W_mid[o,c] * s[b,c,sp])  (batched NN, KP2=13)
    ngemm_kernel<<<dim3(DMDL / GBN, LSEQ / GBM, BATCH), blk>>>(
        W_mid, LSEQ, s, DMDL, bstride, t, DMDL, bstride, LSEQ, DMDL, LSEQ);
    // ---- stage 2: mamba2 -> s
    run_mamba(t, m2_Win, m2_convw, m2_convb, m2_Wx, m2_Wdt, m2_bdt,
              m2_Alog, m2_D, m2_Wout, xz, xi, dbl, dt, y, s);
    ln_kernel<<<MROWS, blk>>>(s, ln2_g, ln2_b);

    // ---- residual path: r = silu(x @ W_spa^T + b_spa)
    tgemm_kernel<2><<<dim3(DMDL / GBN, MROWS / GBM), blk, TG_SMEM_B>>>(
        x, DMDL, W_spa, DMDL, b_spa, r, DMDL, MROWS, DMDL, DMDL);
    // r2 = silu(channel-mix with W_res)   (batched NN, KP2=13)
    ngemm_kernel<<<dim3(DMDL / GBN, LSEQ / GBM, BATCH), blk>>>(
        W_res, LSEQ, r, DMDL, bstride, r2, DMDL, bstride, LSEQ, DMDL, LSEQ);

    // ---- out = silu(s + r2)
    final_kernel<<<(MROWS * DMDL) / 256, blk>>>(s, r2, out);
}

// round 17
// speedup vs baseline: 1.0303x; 1.0303x over previous
#include <cuda_runtime.h>
#include <cuda_bf16.h>
#include <math.h>
#include <stdint.h>

// Problem constants
#define BATCH 16
#define LSEQ  256
#define DMDL  1024           // dm == di
#define DTOT  68             // dtr + 2*n
#define DTR   64
#define MROWS (BATCH*LSEQ)   // 4096

// ---------------- scratch (device globals; no allocations allowed) ----------
__device__ float g_xz [BATCH*LSEQ*2*DMDL];
__device__ float g_xi [BATCH*LSEQ*DMDL];
__device__ float g_dbl[BATCH*LSEQ*DTOT];
__device__ float g_dt [BATCH*LSEQ*DMDL];
__device__ float g_y  [BATCH*LSEQ*DMDL];
__device__ float g_s  [BATCH*LSEQ*DMDL];
__device__ float g_t  [BATCH*LSEQ*DMDL];
__device__ float g_r  [BATCH*LSEQ*DMDL];
__device__ float g_r2 [BATCH*LSEQ*DMDL];

// ---------------- helpers ----------------------------------------------------
__device__ __forceinline__ float silu_f(float v) {
    return v / (1.0f + expf(-v));
}
__device__ __forceinline__ float softplus_f(float v) {
    return fmaxf(v, 0.0f) + log1pf(expf(-fabsf(v)));
}
__device__ __forceinline__ unsigned pack_bf2(__nv_bfloat16 a, __nv_bfloat16 b) {
    __nv_bfloat162 t(a, b);          // a -> low half, b -> high half
    return *reinterpret_cast<unsigned*>(&t);
}
__device__ __forceinline__ void bf16_split(float x, __nv_bfloat16& h, __nv_bfloat16& l) {
    h = __float2bfloat16_rn(x);
    l = __float2bfloat16_rn(x - __bfloat162float(h));
}
__device__ __forceinline__ void split_pack4(float4 v, uint2& h, uint2& l) {
    __nv_bfloat16 hx, hy, hz, hw, lx, ly, lz, lw;
    bf16_split(v.x, hx, lx);
    bf16_split(v.y, hy, ly);
    bf16_split(v.z, hz, lz);
    bf16_split(v.w, hw, lw);
    h.x = pack_bf2(hx, hy); h.y = pack_bf2(hz, hw);
    l.x = pack_bf2(lx, ly); l.y = pack_bf2(lz, lw);
}
__device__ __forceinline__ void mma_bf16(float* c, const unsigned* a, const unsigned* b) {
    asm volatile(
        "mma.sync.aligned.m16n8k16.row.col.f32.bf16.bf16.f32 "
        "{%0,%1,%2,%3},{%4,%5,%6,%7},{%8,%9},{%0,%1,%2,%3};\n"
        : "+f"(c[0]), "+f"(c[1]), "+f"(c[2]), "+f"(c[3])
        : "r"(a[0]), "r"(a[1]), "r"(a[2]), "r"(a[3]), "r"(b[0]), "r"(b[1]));
}

// ================== 3x-bf16 HMMA GEMM, BT (X @ W^T) — R15 config ==============
// C[m,n] = epi( sum_k A[m,k]*B[n,k] );  M%128==0, K%16==0
// NG=false: N%128==0 assumed (no guards, hot path).  NG=true: N arbitrary.
// KP=12: fragment LDS g*12+tg mod 32 all distinct -> conflict-free; uint2 STS.
// Static smem (24KB), two barriers per k-iter (measured best config).
// EPI: 0 none, 2 silu(v+bias[n]), 3 softplus(v+bias[n])
#define GBM 128
#define GBN 128
#define GBK 16
#define KP  12

template<int EPI, bool NG>
__global__ __launch_bounds__(256, 2)
void tgemm_kernel(const float* __restrict__ A, int lda,
                  const float* __restrict__ B, int ldb,
                  const float* __restrict__ bias,
                  float* __restrict__ C, int ldc,
                  int M, int N, int K)
{
    __shared__ unsigned As_hi[GBM][KP];
    __shared__ unsigned As_lo[GBM][KP];
    __shared__ unsigned Bs_hi[GBN][KP];
    __shared__ unsigned Bs_lo[GBN][KP];

    const int m0 = blockIdx.y * GBM;
    const int n0 = blockIdx.x * GBN;
    const int tid = threadIdx.x;
    const int warp = tid >> 5, lane = tid & 31;
    const int wm = warp & 1;
    const int wn = warp >> 1;
    const int g  = lane >> 2;
    const int tg = lane & 3;

    float acc[4][4][4];
    #pragma unroll
    for (int mi = 0; mi < 4; mi++)
        #pragma unroll
        for (int ni = 0; ni < 4; ni++)
            #pragma unroll
            for (int q = 0; q < 4; q++) acc[mi][ni][q] = 0.0f;

    const int a_r  = tid >> 2;
    const int a_c4 = (tid & 3) * 4;
    const int a_cw = a_c4 >> 1;

    const bool bok0 = !NG || (n0 + a_r)      < N;
    const bool bok1 = !NG || (n0 + a_r + 64) < N;
    const float4 fz = make_float4(0.f, 0.f, 0.f, 0.f);

    float4 pa[2], pb[2];

    #pragma unroll
    for (int i = 0; i < 2; i++) {
        pa[i] = *(const float4*)(A + (size_t)(m0 + a_r + i * 64) * lda + a_c4);
        const bool ok = i ? bok1 : bok0;
        pb[i] = ok ? *(const float4*)(B + (size_t)(n0 + a_r + i * 64) * ldb + a_c4) : fz;
    }

    int k0 = 0;
    while (true) {
        #pragma unroll
        for (int i = 0; i < 2; i++) {
            uint2 h, l;
            split_pack4(pa[i], h, l);
            *(uint2*)&As_hi[a_r + i * 64][a_cw] = h;
            *(uint2*)&As_lo[a_r + i * 64][a_cw] = l;
            split_pack4(pb[i], h, l);
            *(uint2*)&Bs_hi[a_r + i * 64][a_cw] = h;
            *(uint2*)&Bs_lo[a_r + i * 64][a_cw] = l;
        }
        __syncthreads();

        const int kn = k0 + GBK;
        const bool more = kn < K;
        if (more) {
            #pragma unroll
            for (int i = 0; i < 2; i++) {
                pa[i] = *(const float4*)(A + (size_t)(m0 + a_r + i * 64) * lda + kn + a_c4);
                const bool ok = i ? bok1 : bok0;
                pb[i] = ok ? *(const float4*)(B + (size_t)(n0 + a_r + i * 64) * ldb + kn + a_c4) : fz;
            }
        }

        {
            unsigned bh[4][2], bl[4][2];
            #pragma unroll
            for (int ni = 0; ni < 4; ni++) {
                const int c = wn * 32 + ni * 8 + g;
                bh[ni][0] = Bs_hi[c][tg];
                bh[ni][1] = Bs_hi[c][tg + 4];
                bl[ni][0] = Bs_lo[c][tg];
                bl[ni][1] = Bs_lo[c][tg + 4];
            }
            #pragma unroll
            for (int mi = 0; mi < 4; mi++) {
                const int r = wm * 64 + mi * 16 + g;
                unsigned ah[4], al[4];
                ah[0] = As_hi[r    ][tg];
                ah[1] = As_hi[r + 8][tg];
                ah[2] = As_hi[r    ][tg + 4];
                ah[3] = As_hi[r + 8][tg + 4];
                al[0] = As_lo[r    ][tg];
                al[1] = As_lo[r + 8][tg];
                al[2] = As_lo[r    ][tg + 4];
                al[3] = As_lo[r + 8][tg + 4];
                #pragma unroll
                for (int ni = 0; ni < 4; ni++) {
                    mma_bf16(acc[mi][ni], ah, bh[ni]);   // hi*hi
                    mma_bf16(acc[mi][ni], ah, bl[ni]);   // hi*lo
                    mma_bf16(acc[mi][ni], al, bh[ni]);   // lo*hi
                }
            }
        }

        if (!more) break;
        __syncthreads();
        k0 = kn;
    }

    #pragma unroll
    for (int mi = 0; mi < 4; mi++) {
        const int r = m0 + wm * 64 + mi * 16 + g;
        #pragma unroll
        for (int ni = 0; ni < 4; ni++) {
            const int c = n0 + wn * 32 + ni * 8 + tg * 2;
            if (NG && c >= N) continue;
            float v0 = acc[mi][ni][0];
            float v1 = acc[mi][ni][1];
            float v2 = acc[mi][ni][2];
            float v3 = acc[mi][ni][3];
            if (EPI == 2 || EPI == 3) {
                const float bb0 = bias[c], bb1 = bias[c + 1];
                v0 += bb0; v1 += bb1; v2 += bb0; v3 += bb1;
            }
            if (EPI == 2) {
                v0 = silu_f(v0); v1 = silu_f(v1);
                v2 = silu_f(v2); v3 = silu_f(v3);
            }
            if (EPI == 3) {
                v0 = softplus_f(v0); v1 = softplus_f(v1);
                v2 = softplus_f(v2); v3 = softplus_f(v3);
            }
            *(float2*)&C[(size_t)r * ldc + c]       = make_float2(v0, v1);
            *(float2*)&C[(size_t)(r + 8) * ldc + c] = make_float2(v2, v3);
        }
    }
}

// ================== 3x-bf16 HMMA GEMM, NN channel-mix (W_mid/W_res) ==========
// C[m,n] = silu( sum_k A[m,k]*B[k,n] ), batched over blockIdx.z.
// KP2=13: odd u16 stride kills B-scatter store conflicts (measured 63->38us).
#define KP2 13

__global__ __launch_bounds__(256, 2)
void ngemm_kernel(const float* __restrict__ A, int lda,
                  const float* __restrict__ B, int ldb, size_t sB,
                  float* __restrict__ C, int ldc, size_t sC,
                  int M, int N, int K)
{
    __shared__ unsigned As_hi[GBM][KP2];
    __shared__ unsigned As_lo[GBM][KP2];
    __shared__ unsigned Bs_hi[GBN][KP2];
    __shared__ unsigned Bs_lo[GBN][KP2];

    const int bz = blockIdx.z;
    B += sB * bz; C += sC * bz;

    const int m0 = blockIdx.y * GBM;
    const int n0 = blockIdx.x * GBN;
    const int tid = threadIdx.x;
    const int warp = tid >> 5, lane = tid & 31;
    const int wm = warp & 1;
    const int wn = warp >> 1;
    const int g  = lane >> 2;
    const int tg = lane & 3;

    float acc[4][4][4];
    #pragma unroll
    for (int mi = 0; mi < 4; mi++)
        #pragma unroll
        for (int ni = 0; ni < 4; ni++)
            #pragma unroll
            for (int q = 0; q < 4; q++) acc[mi][ni][q] = 0.0f;

    const int a_r  = tid >> 2;
    const int a_c4 = (tid & 3) * 4;
    const int a_cw = a_c4 >> 1;
    const int b_kr = tid >> 5;
    const int b_nc = (tid & 31) * 4;

    float4 pa[2], pb[2];

    #pragma unroll
    for (int i = 0; i < 2; i++) {
        pa[i] = *(const float4*)(A + (size_t)(m0 + a_r + i * 64) * lda + a_c4);
        pb[i] = *(const float4*)(B + (size_t)(b_kr + i * 8) * ldb + n0 + b_nc);
    }

    unsigned short* Bs_hi16 = (unsigned short*)Bs_hi;
    unsigned short* Bs_lo16 = (unsigned short*)Bs_lo;

    int k0 = 0;
    while (true) {
        #pragma unroll
        for (int i = 0; i < 2; i++) {
            uint2 h, l;
            split_pack4(pa[i], h, l);
            const int ar = a_r + i * 64;
            As_hi[ar][a_cw]     = h.x;
            As_hi[ar][a_cw + 1] = h.y;
            As_lo[ar][a_cw]     = l.x;
            As_lo[ar][a_cw + 1] = l.y;

            const int k = b_kr + i * 8;
            const float* pv = &pb[i].x;
            #pragma unroll
            for (int j = 0; j < 4; j++) {
                __nv_bfloat16 hh, ll;
                bf16_split(pv[j], hh, ll);
                Bs_hi16[(b_nc + j) * (2 * KP2) + k] = *(unsigned short*)&hh;
                Bs_lo16[(b_nc + j) * (2 * KP2) + k] = *(unsigned short*)&ll;
            }
        }
        __syncthreads();

        const int kn = k0 + GBK;
        const bool more = kn < K;
        if (more) {
            #pragma unroll
            for (int i = 0; i < 2; i++) {
                pa[i] = *(const float4*)(A + (size_t)(m0 + a_r + i * 64) * lda + kn + a_c4);
                pb[i] = *(const float4*)(B + (size_t)(kn + b_kr + i * 8) * ldb + n0 + b_nc);
            }
        }

        {
            unsigned bh[4][2], bl[4][2];
            #pragma unroll
            for (int ni = 0; ni < 4; ni++) {
                const int c = wn * 32 + ni * 8 + g;
                bh[ni][0] = Bs_hi[c][tg];
                bh[ni][1] = Bs_hi[c][tg + 4];
                bl[ni][0] = Bs_lo[c][tg];
                bl[ni][1] = Bs_lo[c][tg + 4];
            }
            #pragma unroll
            for (int mi = 0; mi < 4; mi++) {
                const int r = wm * 64 + mi * 16 + g;
                unsigned ah[4], al[4];
                ah[0] = As_hi[r    ][tg];
                ah[1] = As_hi[r + 8][tg];
                ah[2] = As_hi[r    ][tg + 4];
                ah[3] = As_hi[r + 8][tg + 4];
                al[0] = As_lo[r    ][tg];
                al[1] = As_lo[r + 8][tg];
                al[2] = As_lo[r    ][tg + 4];
                al[3] = As_lo[r + 8][tg + 4];
                #pragma unroll
                for (int ni = 0; ni < 4; ni++) {
                    mma_bf16(acc[mi][ni], ah, bh[ni]);
                    mma_bf16(acc[mi][ni], ah, bl[ni]);
                    mma_bf16(acc[mi][ni], al, bh[ni]);
                }
            }
        }

        if (!more) break;
        __syncthreads();
        k0 = kn;
    }

    #pragma unroll
    for (int mi = 0; mi < 4; mi++) {
        const int r = m0 + wm * 64 + mi * 16 + g;
        #pragma unroll
        for (int ni = 0; ni < 4; ni++) {
            const int c = n0 + wn * 32 + ni * 8 + tg * 2;
            float v0 = silu_f(acc[mi][ni][0]);
            float v1 = silu_f(acc[mi][ni][1]);
            float v2 = silu_f(acc[mi][ni][2]);
            float v3 = silu_f(acc[mi][ni][3]);
            *(float2*)&C[(size_t)r * ldc + c]       = make_float2(v0, v1);
            *(float2*)&C[(size_t)(r + 8) * ldc + c] = make_float2(v2, v3);
        }
    }
}

// ---------------- depthwise causal conv (k=4) + silu --------------------------
__global__ __launch_bounds__(256)
void conv_silu_kernel(const float* __restrict__ xz,
                      const float* __restrict__ convw,
                      const float* __restrict__ convb,
                      float* __restrict__ xi)
{
    const int idx = blockIdx.x * 256 + threadIdx.x;
    const int d = idx & (DMDL - 1);
    const int bl = idx >> 10;
    const int l = bl & (LSEQ - 1);
    const int b = bl >> 8;

    float w0 = convw[d * 4 + 0], w1 = convw[d * 4 + 1];
    float w2 = convw[d * 4 + 2], w3 = convw[d * 4 + 3];

    const size_t base = ((size_t)b * LSEQ) * (2 * DMDL) + d;
    float acc = convb[d];
    if (l >= 3) acc = fmaf(w0, xz[base + (size_t)(l - 3) * (2 * DMDL)], acc);
    if (l >= 2) acc = fmaf(w1, xz[base + (size_t)(l - 2) * (2 * DMDL)], acc);
    if (l >= 1) acc = fmaf(w2, xz[base + (size_t)(l - 1) * (2 * DMDL)], acc);
    acc = fmaf(w3, xz[base + (size_t)l * (2 * DMDL)], acc);

    xi[idx] = silu_f(acc);
}

// ---------------- selective-scan (n=2) fused with skip + gate -----------------
__global__ __launch_bounds__(256)
void scan_kernel(const float* __restrict__ dt,
                 const float* __restrict__ xi,
                 const float* __restrict__ xz,
                 const float* __restrict__ dbl,
                 const float* __restrict__ Alog,
                 const float* __restrict__ Dp,
                 float* __restrict__ y)
{
    const int b = blockIdx.x >> 2;
    const int chunk = blockIdx.x & 3;
    const int d = chunk * 256 + threadIdx.x;

    const float A0 = -expf(Alog[d * 2 + 0]);
    const float A1 = -expf(Alog[d * 2 + 1]);
    const float Dd = Dp[d];

    float h0 = 0.0f, h1 = 0.0f;

    #pragma unroll 4
    for (int l = 0; l < LSEQ; l++) {
        const int bl = b * LSEQ + l;
        const size_t idx = (size_t)bl * DMDL + d;
        const float dtv = dt[idx];
        const float xiv = xi[idx];
        const float zv  = xz[(size_t)bl * (2 * DMDL) + DMDL + d];
        const float* bc = dbl + (size_t)bl * DTOT + DTR;
        const float B0 = bc[0], B1 = bc[1], C0 = bc[2], C1 = bc[3];

        const float dBx = dtv * xiv;
        h0 = fmaf(expf(dtv * A0), h0, dBx * B0);
        h1 = fmaf(expf(dtv * A1), h1, dBx * B1);

        float yv = fmaf(h0, C0, h1 * C1);
        yv = fmaf(Dd, xiv, yv);
        y[idx] = yv * silu_f(zv);
    }
}

// ---------------- LayerNorm (in-place) ----------------------------------------
__global__ __launch_bounds__(256)
void ln_kernel(float* __restrict__ x,
               const float* __restrict__ g,
               const float* __restrict__ b)
{
    __shared__ float red[256];
    const int tid = threadIdx.x;
    float* p = x + (size_t)blockIdx.x * DMDL;

    float v[4];
    float s = 0.0f;
    #pragma unroll
    for (int i = 0; i < 4; i++) { v[i] = p[tid + i * 256]; s += v[i]; }

    red[tid] = s; __syncthreads();
    for (int o = 128; o > 0; o >>= 1) {
        if (tid < o) red[tid] += red[tid + o];
        __syncthreads();
    }
    const float mean = red[0] * (1.0f / DMDL);
    __syncthreads();

    float sq = 0.0f;
    #pragma unroll
    for (int i = 0; i < 4; i++) { float dd = v[i] - mean; sq += dd * dd; }
    red[tid] = sq; __syncthreads();
    for (int o = 128; o > 0; o >>= 1) {
        if (tid < o) red[tid] += red[tid + o];
        __syncthreads();
    }
    const float rstd = rsqrtf(red[0] * (1.0f / DMDL) + 1e-5f);

    #pragma unroll
    for (int i = 0; i < 4; i++) {
        const int c = tid + i * 256;
        p[c] = (v[i] - mean) * rstd * g[c] + b[c];
    }
}

// ---------------- final fused add + silu --------------------------------------
__global__ __launch_bounds__(256)
void final_kernel(const float* __restrict__ s,
                  const float* __restrict__ r,
                  float* __restrict__ out)
{
    const int i = blockIdx.x * 256 + threadIdx.x;
    out[i] = silu_f(s[i] + r[i]);
}

// ---------------- host orchestration ------------------------------------------
static void run_mamba(const float* X,
                      const float* Win, const float* convw, const float* convb,
                      const float* Wx, const float* Wdt, const float* bdt,
                      const float* Alog, const float* Dp, const float* Wout,
                      float* xz, float* xi, float* dbl, float* dt, float* y,
                      float* out)
{
    dim3 blk(256);
    // xz = X @ Win^T   (4096 x 2048, K=1024)
    tgemm_kernel<0, false><<<dim3((2 * DMDL) / GBN, MROWS / GBM), blk>>>(
        X, DMDL, Win, DMDL, nullptr, xz, 2 * DMDL, MROWS, 2 * DMDL, DMDL);
    // xi = silu(conv(xz[:,:,:di]))
    conv_silu_kernel<<<(MROWS * DMDL) / 256, blk>>>(xz, convw, convb, xi);
    // dbl = xi @ Wx^T  (4096 x 68, K=1024) — tensor, N-guarded
    tgemm_kernel<0, true><<<dim3(1, MROWS / GBM), blk>>>(
        xi, DMDL, Wx, DMDL, nullptr, dbl, DTOT, MROWS, DTOT, DMDL);
    // dt = softplus(dbl[:,:64] @ Wdt^T + bdt)  (4096 x 1024, K=64) — tensor
    tgemm_kernel<3, false><<<dim3(DMDL / GBN, MROWS / GBM), blk>>>(
        dbl, DTOT, Wdt, DTR, bdt, dt, DMDL, MROWS, DMDL, DTR);
    // selective scan + skip + gate
    scan_kernel<<<BATCH * (DMDL / 256), blk>>>(dt, xi, xz, dbl, Alog, Dp, y);
    // out = y @ Wout^T  (4096 x 1024, K=1024)
    tgemm_kernel<0, false><<<dim3(DMDL / GBN, MROWS / GBM), blk>>>(
        y, DMDL, Wout, DMDL, nullptr, out, DMDL, MROWS, DMDL, DMDL);
}

extern "C" void kernel_launch(void* const* d_in, const int* in_sizes, int n_in,
                              void* d_out, int out_size)
{
    (void)in_sizes; (void)n_in; (void)out_size;

    const float* x        = (const float*)d_in[0];
    const float* m1_Win   = (const float*)d_in[1];
    const float* m1_convw = (const float*)d_in[2];
    const float* m1_convb = (const float*)d_in[3];
    const float* m1_Wx    = (const float*)d_in[4];
    const float* m1_Wdt   = (const float*)d_in[5];
    const float* m1_bdt   = (const float*)d_in[6];
    const float* m1_Alog  = (const float*)d_in[7];
    const float* m1_D     = (const float*)d_in[8];
    const float* m1_Wout  = (const float*)d_in[9];
    const float* m2_Win   = (const float*)d_in[10];
    const float* m2_convw = (const float*)d_in[11];
    const float* m2_convb = (const float*)d_in[12];
    const float* m2_Wx    = (const float*)d_in[13];
    const float* m2_Wdt   = (const float*)d_in[14];
    const float* m2_bdt   = (const float*)d_in[15];
    const float* m2_Alog  = (const float*)d_in[16];
    const float* m2_D     = (const float*)d_in[17];
    const float* m2_Wout  = (const float*)d_in[18];
    const float* ln1_g    = (const float*)d_in[19];
    const float* ln1_b    = (const float*)d_in[20];
    const float* ln2_g    = (const float*)d_in[21];
    const float* ln2_b    = (const float*)d_in[22];
    const float* W_mid    = (const float*)d_in[23];
    const float* W_spa    = (const float*)d_in[24];
    const float* b_spa    = (const float*)d_in[25];
    const float* W_res    = (const float*)d_in[26];
    float* out = (float*)d_out;

    void *p_xz, *p_xi, *p_dbl, *p_dt, *p_y, *p_s, *p_t, *p_r, *p_r2;
    cudaGetSymbolAddress(&p_xz,  g_xz);
    cudaGetSymbolAddress(&p_xi,  g_xi);
    cudaGetSymbolAddress(&p_dbl, g_dbl);
    cudaGetSymbolAddress(&p_dt,  g_dt);
    cudaGetSymbolAddress(&p_y,   g_y);
    cudaGetSymbolAddress(&p_s,   g_s);
    cudaGetSymbolAddress(&p_t,   g_t);
    cudaGetSymbolAddress(&p_r,   g_r);
    cudaGetSymbolAddress(&p_r2,  g_r2);
    float* xz = (float*)p_xz;  float* xi = (float*)p_xi;  float* dbl = (float*)p_dbl;
    float* dt = (float*)p_dt;  float* y  = (float*)p_y;   float* s   = (float*)p_s;
    float* t  = (float*)p_t;   float* r  = (float*)p_r;   float* r2  = (float*)p_r2;

    dim3 blk(256);
    const size_t bstride = (size_t)LSEQ * DMDL;

    // ---- stage 1: mamba1 -> s
    run_mamba(x, m1_Win, m1_convw, m1_convb, m1_Wx, m1_Wdt, m1_bdt,
              m1_Alog, m1_D, m1_Wout, xz, xi, dbl, dt, y, s);
    ln_kernel<<<MROWS, blk>>>(s, ln1_g, ln1_b);
    // t[b,o,sp] = silu(sum_c W_mid[o,c] * s[b,c,sp])  (batched NN, KP2=13)
    ngemm_kernel<<<dim3(DMDL / GBN, LSEQ / GBM, BATCH), blk>>>(
        W_mid, LSEQ, s, DMDL, bstride, t, DMDL, bstride, LSEQ, DMDL, LSEQ);
    // ---- stage 2: mamba2 -> s
    run_mamba(t, m2_Win, m2_convw, m2_convb, m2_Wx, m2_Wdt, m2_bdt,
              m2_Alog, m2_D, m2_Wout, xz, xi, dbl, dt, y, s);
    ln_kernel<<<MROWS, blk>>>(s, ln2_g, ln2_b);

    // ---- residual path: r = silu(x @ W_spa^T + b_spa)
    tgemm_kernel<2, false><<<dim3(DMDL / GBN, MROWS / GBM), blk>>>(
        x, DMDL, W_spa, DMDL, b_spa, r, DMDL, MROWS, DMDL, DMDL);
    // r2 = silu(channel-mix with W_res)   (batched NN, KP2=13)
    ngemm_kernel<<<dim3(DMDL / GBN, LSEQ / GBM, BATCH), blk>>>(
        W_res, LSEQ, r, DMDL, bstride, r2, DMDL, bstride, LSEQ, DMDL, LSEQ);

    // ---- out = silu(s + r2)
    final_kernel<<<(MROWS * DMDL) / 256, blk>>>(s, r2, out);
}